// round 9
// baseline (speedup 1.0000x reference)
#include <cuda_runtime.h>
#include <cuda_bf16.h>
#include <math_constants.h>

// Problem constants
#define BATCH   2
#define NPTS    8192
#define KNN     11        // k+1 including self
#define LEN_IN  66        // 3*11 + 3*10 + 3
#define TPB     128
#define NGROUP  4         // split-K over candidates
#define QPB     (TPB / NGROUP)        // 32 queries per block
#define GRANGE  (NPTS / NGROUP)       // 2048 candidates per group
#define CHUNK   512                   // candidates per group per smem iteration
#define NITER   (GRANGE / CHUNK)      // 4

// Collapsed weights (device scratch; no allocations allowed)
__device__ float g_W12[LEN_IN * 16];
__device__ float g_Wc [LEN_IN * 6];
__device__ float g_bc [6];

// ---------------------------------------------------------------------------
// Prologue: collapse W1@W2@W3 and the bias chain (tiny, one block).
// The reference MLP has no activation functions, so the whole head is affine:
//   pred = feats @ (W1@W2@W3) + ((b1@W2 + b2)@W3 + b3)
// ---------------------------------------------------------------------------
__global__ void combine_weights_kernel(const float* __restrict__ W1,
                                       const float* __restrict__ b1,
                                       const float* __restrict__ W2,
                                       const float* __restrict__ b2,
                                       const float* __restrict__ W3,
                                       const float* __restrict__ b3)
{
    int t = threadIdx.x;
    // W12 = W1[66,32] @ W2[32,16]
    for (int e = t; e < LEN_IN * 16; e += blockDim.x) {
        int r = e / 16, c = e % 16;
        float s = 0.f;
        for (int k = 0; k < 32; ++k) s += W1[r * 32 + k] * W2[k * 16 + c];
        g_W12[e] = s;
    }
    __syncthreads();
    // Wc = W12[66,16] @ W3[16,6]
    for (int e = t; e < LEN_IN * 6; e += blockDim.x) {
        int r = e / 6, c = e % 6;
        float s = 0.f;
        for (int k = 0; k < 16; ++k) s += g_W12[r * 16 + k] * W3[k * 6 + c];
        g_Wc[e] = s;
    }
    // bc = ((b1@W2)+b2)@W3 + b3
    if (t < 6) {
        float s = b3[t];
        for (int k = 0; k < 16; ++k) {
            float tb = b2[k];
            for (int m = 0; m < 32; ++m) tb += b1[m] * W2[m * 16 + k];
            s += tb * W3[k * 6 + t];
        }
        g_bc[t] = s;
    }
}

// ---------------------------------------------------------------------------
// Main fused kernel: split-K brute-force kNN (top-11 by d2) + exact merge +
// gather + collapsed linear head.
//   Block = 32 queries x 4 candidate groups (128 threads).
//   Warp w scans candidate range [w*2048, (w+1)*2048) for its 32 queries.
//   All lanes of a warp read the same s_tile entry -> broadcast LDS.
//   Numerics and insert semantics are EXACTLY the round-5 passing kernel's
//   (fma-based sq/dot, serial strict-'<' swap chain).
// ---------------------------------------------------------------------------
__global__ void __launch_bounds__(TPB)
knn_mlp_kernel(const float* __restrict__ pos,
               const float* __restrict__ vel,
               const float* __restrict__ initc,
               float* __restrict__ out)
{
    __shared__ float4 s_tile[NGROUP * CHUNK];      // per-group candidate chunks
    __shared__ float  s_md[TPB * KNN];             // partial top-11 distances
    __shared__ int    s_mi[TPB * KNN];             // partial top-11 indices
    __shared__ float  s_Wc[LEN_IN * 6];
    __shared__ float  s_bc[6];

    const int tid  = threadIdx.x;
    const int grp  = tid >> 5;                     // 0..3  (== warp id)
    const int qloc = tid & (QPB - 1);              // query within block
    const int q    = blockIdx.x * QPB + qloc;      // global query id
    const int bb   = q >> 13;                      // q / 8192 (batch)
    const int i    = q & (NPTS - 1);

    const float* __restrict__ bpos = pos + (size_t)bb * NPTS * 3;
    const float* __restrict__ bvel = vel + (size_t)bb * NPTS * 3;

    for (int t = tid; t < LEN_IN * 6; t += TPB) s_Wc[t] = g_Wc[t];
    if (tid < 6) s_bc[tid] = g_bc[tid];

    // Query point; sq computed with the SAME op sequence as the tile loader so
    // the self-distance is exactly 0 (round-5 passing recipe, unchanged).
    const float qx = bpos[i * 3 + 0];
    const float qy = bpos[i * 3 + 1];
    const float qz = bpos[i * 3 + 2];
    float qs = qx * qx; qs = fmaf(qy, qy, qs); qs = fmaf(qz, qz, qs);

    // Per-group sorted top-11 (ascending), register-resident.
    float bd[KNN];
    int   bi[KNN];
#pragma unroll
    for (int k = 0; k < KNN; ++k) { bd[k] = CUDART_INF_F; bi[k] = 0; }

    const float4* __restrict__ mytile = s_tile + grp * CHUNK;

    for (int it = 0; it < NITER; ++it) {
        __syncthreads();
        // Cooperative load of all groups' chunks: (x,y,z,sq)
        for (int t = tid; t < NGROUP * CHUNK; t += TPB) {
            const int g  = t >> 9;                        // t / CHUNK
            const int r  = t & (CHUNK - 1);
            const int j  = g * GRANGE + it * CHUNK + r;   // global candidate id
            const float x = bpos[j * 3 + 0];
            const float y = bpos[j * 3 + 1];
            const float z = bpos[j * 3 + 2];
            float s = x * x; s = fmaf(y, y, s); s = fmaf(z, z, s);
            s_tile[t] = make_float4(x, y, z, s);
        }
        __syncthreads();

        const int idxbase = grp * GRANGE + it * CHUNK;
#pragma unroll 8
        for (int t = 0; t < CHUNK; ++t) {
            const float4 p = mytile[t];
            float d = qx * p.x; d = fmaf(qy, p.y, d); d = fmaf(qz, p.z, d);
            const float d2 = fmaf(-2.0f, d, qs + p.w);
            if (d2 < bd[KNN - 1]) {
                // Serial strict-'<' sorted insert — EXACT semantics of the
                // passing round-5 kernel (matches the reference's tie
                // behavior on duplicate d2 values; do not "optimize").
                float dv = d2; int id = idxbase + t;
#pragma unroll
                for (int k = 0; k < KNN; ++k) {
                    if (dv < bd[k]) {
                        float td = bd[k]; bd[k] = dv; dv = td;
                        int   ti = bi[k]; bi[k] = id; id = ti;
                    }
                }
            }
        }
    }

    // Publish partial lists.
#pragma unroll
    for (int k = 0; k < KNN; ++k) {
        s_md[tid * KNN + k] = bd[k];
        s_mi[tid * KNN + k] = bi[k];
    }
    __syncthreads();

    // Threads 0..31 merge their query's four sorted lists sequentially.
    // On equal d2 the lower group wins (its indices are all lower) —
    // same tie rule as the round-5 two-way merge.
    if (tid < QPB) {
        float m1d[KNN]; int m1i[KNN];
        // merge group 0 with group 1
        {
            const int a = (0 * QPB + qloc) * KNN;
            const int b = (1 * QPB + qloc) * KNN;
            int ia = 0, ib = 0;
#pragma unroll
            for (int k = 0; k < KNN; ++k) {
                const float da = s_md[a + ia];
                const float db = s_md[b + ib];
                if (da <= db) { m1d[k] = da; m1i[k] = s_mi[a + ia]; ++ia; }
                else          { m1d[k] = db; m1i[k] = s_mi[b + ib]; ++ib; }
            }
        }
        float m2d[KNN]; int m2i[KNN];
        // merge (0,1) with group 2
        {
            const int b = (2 * QPB + qloc) * KNN;
            int ia = 0, ib = 0;
#pragma unroll
            for (int k = 0; k < KNN; ++k) {
                const float da = m1d[ia];
                const float db = s_md[b + ib];
                if (da <= db) { m2d[k] = da; m2i[k] = m1i[ia]; ++ia; }
                else          { m2d[k] = db; m2i[k] = s_mi[b + ib]; ++ib; }
            }
        }
        int fi[KNN];
        // merge (0,1,2) with group 3
        {
            const int b = (3 * QPB + qloc) * KNN;
            int ia = 0, ib = 0;
#pragma unroll
            for (int k = 0; k < KNN; ++k) {
                const float da = m2d[ia];
                const float db = s_md[b + ib];
                if (da <= db) { fi[k] = m2i[ia]; ++ia; }
                else          { fi[k] = s_mi[b + ib]; ++ib; }
            }
        }

        // ---- gather features and apply collapsed linear head ----
        float acc[6];
#pragma unroll
        for (int c = 0; c < 6; ++c) acc[c] = s_bc[c];

        // rows 0..32: neighbor velocities (incl. self, rank order)
#pragma unroll
        for (int r = 0; r < KNN; ++r) {
            const int j = fi[r];
            const float vx = bvel[j * 3 + 0];
            const float vy = bvel[j * 3 + 1];
            const float vz = bvel[j * 3 + 2];
            const int row = 3 * r;
#pragma unroll
            for (int c = 0; c < 6; ++c) {
                acc[c] = fmaf(vx, s_Wc[(row + 0) * 6 + c], acc[c]);
                acc[c] = fmaf(vy, s_Wc[(row + 1) * 6 + c], acc[c]);
                acc[c] = fmaf(vz, s_Wc[(row + 2) * 6 + c], acc[c]);
            }
        }
        // rows 33..62: neighbor position offsets (excl. self)
#pragma unroll
        for (int r = 1; r < KNN; ++r) {
            const int j = fi[r];
            const float ox = bpos[j * 3 + 0] - qx;
            const float oy = bpos[j * 3 + 1] - qy;
            const float oz = bpos[j * 3 + 2] - qz;
            const int row = 33 + 3 * (r - 1);
#pragma unroll
            for (int c = 0; c < 6; ++c) {
                acc[c] = fmaf(ox, s_Wc[(row + 0) * 6 + c], acc[c]);
                acc[c] = fmaf(oy, s_Wc[(row + 1) * 6 + c], acc[c]);
                acc[c] = fmaf(oz, s_Wc[(row + 2) * 6 + c], acc[c]);
            }
        }
        // rows 63..65: init_config
        {
            const float i0 = initc[bb * 3 + 0];
            const float i1 = initc[bb * 3 + 1];
            const float i2 = initc[bb * 3 + 2];
#pragma unroll
            for (int c = 0; c < 6; ++c) {
                acc[c] = fmaf(i0, s_Wc[63 * 6 + c], acc[c]);
                acc[c] = fmaf(i1, s_Wc[64 * 6 + c], acc[c]);
                acc[c] = fmaf(i2, s_Wc[65 * 6 + c], acc[c]);
            }
        }

        float* o = out + (size_t)q * 6;
        o[0] = acc[0] + qx;
        o[1] = acc[1] + qy;
        o[2] = acc[2] + qz;
        o[3] = acc[3];
        o[4] = acc[4];
        o[5] = acc[5];
    }
}

// ---------------------------------------------------------------------------
extern "C" void kernel_launch(void* const* d_in, const int* in_sizes, int n_in,
                              void* d_out, int out_size)
{
    const float* position = (const float*)d_in[0];
    const float* velocity = (const float*)d_in[1];
    const float* initcfg  = (const float*)d_in[2];
    const float* W1 = (const float*)d_in[3];
    const float* b1 = (const float*)d_in[4];
    const float* W2 = (const float*)d_in[5];
    const float* b2 = (const float*)d_in[6];
    const float* W3 = (const float*)d_in[7];
    const float* b3 = (const float*)d_in[8];
    float* out = (float*)d_out;

    combine_weights_kernel<<<1, 256>>>(W1, b1, W2, b2, W3, b3);

    const int total = BATCH * NPTS;           // 16384 queries
    knn_mlp_kernel<<<total / QPB, TPB>>>(position, velocity, initcfg, out);
}

// round 10
// speedup vs baseline: 1.2084x; 1.2084x over previous
#include <cuda_runtime.h>
#include <cuda_bf16.h>
#include <math_constants.h>

// Problem constants
#define BATCH   2
#define NPTS    8192
#define KNN     11        // k+1 including self
#define LEN_IN  66        // 3*11 + 3*10 + 3
#define TPB     128
#define NGROUP  4         // split-K over candidates
#define QPB     (TPB / NGROUP)        // 32 queries per block
#define GRANGE  (NPTS / NGROUP)       // 2048 candidates per group
#define CHUNK   256                   // candidates per group per smem iteration
#define NITER   (GRANGE / CHUNK)      // 8
#define BUCK_CAP    16                // per-thread staging slots
#define BUCK_FLUSH  8                 // flush when any lane reaches this

// Collapsed weights (device scratch; no allocations allowed)
__device__ float g_W12[LEN_IN * 16];
__device__ float g_Wc [LEN_IN * 6];
__device__ float g_bc [6];

// ---------------------------------------------------------------------------
// Prologue: collapse W1@W2@W3 and the bias chain (tiny, one block).
// The reference MLP has no activation functions, so the whole head is affine:
//   pred = feats @ (W1@W2@W3) + ((b1@W2 + b2)@W3 + b3)
// ---------------------------------------------------------------------------
__global__ void combine_weights_kernel(const float* __restrict__ W1,
                                       const float* __restrict__ b1,
                                       const float* __restrict__ W2,
                                       const float* __restrict__ b2,
                                       const float* __restrict__ W3,
                                       const float* __restrict__ b3)
{
    int t = threadIdx.x;
    // W12 = W1[66,32] @ W2[32,16]
    for (int e = t; e < LEN_IN * 16; e += blockDim.x) {
        int r = e / 16, c = e % 16;
        float s = 0.f;
        for (int k = 0; k < 32; ++k) s += W1[r * 32 + k] * W2[k * 16 + c];
        g_W12[e] = s;
    }
    __syncthreads();
    // Wc = W12[66,16] @ W3[16,6]
    for (int e = t; e < LEN_IN * 6; e += blockDim.x) {
        int r = e / 6, c = e % 6;
        float s = 0.f;
        for (int k = 0; k < 16; ++k) s += g_W12[r * 16 + k] * W3[k * 6 + c];
        g_Wc[e] = s;
    }
    // bc = ((b1@W2)+b2)@W3 + b3
    if (t < 6) {
        float s = b3[t];
        for (int k = 0; k < 16; ++k) {
            float tb = b2[k];
            for (int m = 0; m < 32; ++m) tb += b1[m] * W2[m * 16 + k];
            s += tb * W3[k * 6 + t];
        }
        g_bc[t] = s;
    }
}

// ---------------------------------------------------------------------------
// Flush staged (d2, idx) pairs through the EXACT serial strict-'<' sorted
// insert chain (round-5/round-9 passing semantics). Items are replayed in
// scan (ascending index) order; replaying a superset of guard-passing
// candidates is a no-op for non-qualifying ones (list is sorted), so staging
// with a stale threshold is bit-identical to live insertion.
// ---------------------------------------------------------------------------
__device__ __forceinline__ void flush_bucket(const float2* __restrict__ buck,
                                             int& cnt,
                                             float bd[KNN], int bi[KNN],
                                             float& tau)
{
    for (int u = 0; u < cnt; ++u) {
        const float2 e = buck[u];
        float dv = e.x;
        if (dv < bd[KNN - 1]) {
            int id = __float_as_int(e.y);
#pragma unroll
            for (int k = 0; k < KNN; ++k) {
                if (dv < bd[k]) {
                    float td = bd[k]; bd[k] = dv; dv = td;
                    int   ti = bi[k]; bi[k] = id; id = ti;
                }
            }
        }
    }
    cnt = 0;
    tau = bd[KNN - 1];
}

// ---------------------------------------------------------------------------
// Main fused kernel: split-K brute-force kNN (top-11 by d2) with staged
// inserts + exact merge + gather + collapsed linear head.
//   Block = 32 queries x 4 candidate groups (128 threads).
//   Warp w scans candidate range [w*2048, (w+1)*2048) for its 32 queries.
// ---------------------------------------------------------------------------
__global__ void __launch_bounds__(TPB)
knn_mlp_kernel(const float* __restrict__ pos,
               const float* __restrict__ vel,
               const float* __restrict__ initc,
               float* __restrict__ out)
{
    __shared__ float4 s_tile[NGROUP * CHUNK];      // candidate chunks (16KB)
    __shared__ float2 s_buck[TPB * BUCK_CAP];      // per-thread staging (16KB)
    __shared__ float  s_md[TPB * KNN];             // partial top-11 distances
    __shared__ int    s_mi[TPB * KNN];             // partial top-11 indices
    __shared__ float  s_Wc[LEN_IN * 6];
    __shared__ float  s_bc[6];

    const int tid  = threadIdx.x;
    const int grp  = tid >> 5;                     // 0..3  (== warp id)
    const int qloc = tid & (QPB - 1);              // query within block
    const int q    = blockIdx.x * QPB + qloc;      // global query id
    const int bb   = q >> 13;                      // q / 8192 (batch)
    const int i    = q & (NPTS - 1);

    const float* __restrict__ bpos = pos + (size_t)bb * NPTS * 3;
    const float* __restrict__ bvel = vel + (size_t)bb * NPTS * 3;

    for (int t = tid; t < LEN_IN * 6; t += TPB) s_Wc[t] = g_Wc[t];
    if (tid < 6) s_bc[tid] = g_bc[tid];

    // Query point; sq computed with the SAME op sequence as the tile loader so
    // the self-distance is exactly 0 (round-5 passing recipe, unchanged).
    const float qx = bpos[i * 3 + 0];
    const float qy = bpos[i * 3 + 1];
    const float qz = bpos[i * 3 + 2];
    float qs = qx * qx; qs = fmaf(qy, qy, qs); qs = fmaf(qz, qz, qs);

    // Per-group sorted top-11 (ascending), register-resident.
    float bd[KNN];
    int   bi[KNN];
#pragma unroll
    for (int k = 0; k < KNN; ++k) { bd[k] = CUDART_INF_F; bi[k] = 0; }

    float2* const mybuck = s_buck + tid * BUCK_CAP;
    int   cnt = 0;
    float tau = CUDART_INF_F;

    const float4* __restrict__ mytile = s_tile + grp * CHUNK;

    for (int it = 0; it < NITER; ++it) {
        __syncthreads();
        // Cooperative load of all groups' chunks: (x,y,z,sq)
        for (int t = tid; t < NGROUP * CHUNK; t += TPB) {
            const int g  = t >> 8;                        // t / CHUNK
            const int r  = t & (CHUNK - 1);
            const int j  = g * GRANGE + it * CHUNK + r;   // global candidate id
            const float x = bpos[j * 3 + 0];
            const float y = bpos[j * 3 + 1];
            const float z = bpos[j * 3 + 2];
            float s = x * x; s = fmaf(y, y, s); s = fmaf(z, z, s);
            s_tile[t] = make_float4(x, y, z, s);
        }
        __syncthreads();

        const int idxbase = grp * GRANGE + it * CHUNK;
        for (int tb = 0; tb < CHUNK; tb += 8) {
#pragma unroll
            for (int v = 0; v < 8; ++v) {
                const int t = tb + v;
                const float4 p = mytile[t];
                float d = qx * p.x; d = fmaf(qy, p.y, d); d = fmaf(qz, p.z, d);
                const float d2 = fmaf(-2.0f, d, qs + p.w);
                // Cheap staged append (predicated, no warp event):
                if (d2 < tau) {
                    mybuck[cnt] = make_float2(d2, __int_as_float(idxbase + t));
                    ++cnt;
                }
            }
            // Warp-coherent flush when any lane's bucket is half full.
            // (<=8 items can be added between checks; capacity 16 is safe.)
            if (__ballot_sync(0xFFFFFFFFu, cnt >= BUCK_FLUSH))
                flush_bucket(mybuck, cnt, bd, bi, tau);
        }
    }
    // Flush remaining staged candidates.
    flush_bucket(mybuck, cnt, bd, bi, tau);

    // Publish partial lists.
#pragma unroll
    for (int k = 0; k < KNN; ++k) {
        s_md[tid * KNN + k] = bd[k];
        s_mi[tid * KNN + k] = bi[k];
    }
    __syncthreads();

    // Threads 0..31 merge their query's four sorted lists sequentially.
    // On equal d2 the lower group wins (its indices are all lower) —
    // same tie rule as the passing round-9 merge.
    if (tid < QPB) {
        float m1d[KNN]; int m1i[KNN];
        // merge group 0 with group 1
        {
            const int a = (0 * QPB + qloc) * KNN;
            const int b = (1 * QPB + qloc) * KNN;
            int ia = 0, ib = 0;
#pragma unroll
            for (int k = 0; k < KNN; ++k) {
                const float da = s_md[a + ia];
                const float db = s_md[b + ib];
                if (da <= db) { m1d[k] = da; m1i[k] = s_mi[a + ia]; ++ia; }
                else          { m1d[k] = db; m1i[k] = s_mi[b + ib]; ++ib; }
            }
        }
        float m2d[KNN]; int m2i[KNN];
        // merge (0,1) with group 2
        {
            const int b = (2 * QPB + qloc) * KNN;
            int ia = 0, ib = 0;
#pragma unroll
            for (int k = 0; k < KNN; ++k) {
                const float da = m1d[ia];
                const float db = s_md[b + ib];
                if (da <= db) { m2d[k] = da; m2i[k] = m1i[ia]; ++ia; }
                else          { m2d[k] = db; m2i[k] = s_mi[b + ib]; ++ib; }
            }
        }
        int fi[KNN];
        // merge (0,1,2) with group 3
        {
            const int b = (3 * QPB + qloc) * KNN;
            int ia = 0, ib = 0;
#pragma unroll
            for (int k = 0; k < KNN; ++k) {
                const float da = m2d[ia];
                const float db = s_md[b + ib];
                if (da <= db) { fi[k] = m2i[ia]; ++ia; }
                else          { fi[k] = s_mi[b + ib]; ++ib; }
            }
        }

        // ---- gather features and apply collapsed linear head ----
        float acc[6];
#pragma unroll
        for (int c = 0; c < 6; ++c) acc[c] = s_bc[c];

        // rows 0..32: neighbor velocities (incl. self, rank order)
#pragma unroll
        for (int r = 0; r < KNN; ++r) {
            const int j = fi[r];
            const float vx = bvel[j * 3 + 0];
            const float vy = bvel[j * 3 + 1];
            const float vz = bvel[j * 3 + 2];
            const int row = 3 * r;
#pragma unroll
            for (int c = 0; c < 6; ++c) {
                acc[c] = fmaf(vx, s_Wc[(row + 0) * 6 + c], acc[c]);
                acc[c] = fmaf(vy, s_Wc[(row + 1) * 6 + c], acc[c]);
                acc[c] = fmaf(vz, s_Wc[(row + 2) * 6 + c], acc[c]);
            }
        }
        // rows 33..62: neighbor position offsets (excl. self)
#pragma unroll
        for (int r = 1; r < KNN; ++r) {
            const int j = fi[r];
            const float ox = bpos[j * 3 + 0] - qx;
            const float oy = bpos[j * 3 + 1] - qy;
            const float oz = bpos[j * 3 + 2] - qz;
            const int row = 33 + 3 * (r - 1);
#pragma unroll
            for (int c = 0; c < 6; ++c) {
                acc[c] = fmaf(ox, s_Wc[(row + 0) * 6 + c], acc[c]);
                acc[c] = fmaf(oy, s_Wc[(row + 1) * 6 + c], acc[c]);
                acc[c] = fmaf(oz, s_Wc[(row + 2) * 6 + c], acc[c]);
            }
        }
        // rows 63..65: init_config
        {
            const float i0 = initc[bb * 3 + 0];
            const float i1 = initc[bb * 3 + 1];
            const float i2 = initc[bb * 3 + 2];
#pragma unroll
            for (int c = 0; c < 6; ++c) {
                acc[c] = fmaf(i0, s_Wc[63 * 6 + c], acc[c]);
                acc[c] = fmaf(i1, s_Wc[64 * 6 + c], acc[c]);
                acc[c] = fmaf(i2, s_Wc[65 * 6 + c], acc[c]);
            }
        }

        float* o = out + (size_t)q * 6;
        o[0] = acc[0] + qx;
        o[1] = acc[1] + qy;
        o[2] = acc[2] + qz;
        o[3] = acc[3];
        o[4] = acc[4];
        o[5] = acc[5];
    }
}

// ---------------------------------------------------------------------------
extern "C" void kernel_launch(void* const* d_in, const int* in_sizes, int n_in,
                              void* d_out, int out_size)
{
    const float* position = (const float*)d_in[0];
    const float* velocity = (const float*)d_in[1];
    const float* initcfg  = (const float*)d_in[2];
    const float* W1 = (const float*)d_in[3];
    const float* b1 = (const float*)d_in[4];
    const float* W2 = (const float*)d_in[5];
    const float* b2 = (const float*)d_in[6];
    const float* W3 = (const float*)d_in[7];
    const float* b3 = (const float*)d_in[8];
    float* out = (float*)d_out;

    combine_weights_kernel<<<1, 256>>>(W1, b1, W2, b2, W3, b3);

    const int total = BATCH * NPTS;           // 16384 queries
    knn_mlp_kernel<<<total / QPB, TPB>>>(position, velocity, initcfg, out);
}

// round 11
// speedup vs baseline: 1.6776x; 1.3884x over previous
#include <cuda_runtime.h>
#include <cuda_bf16.h>
#include <math_constants.h>

// Problem constants
#define BATCH   2
#define NPTS    8192
#define KNN     11        // k+1 including self
#define LEN_IN  66        // 3*11 + 3*10 + 3
#define TPB     128
#define NGROUP  4         // split-K over candidates
#define QPB     (TPB / NGROUP)        // 32 queries per block
#define GRANGE  (NPTS / NGROUP)       // 2048 candidates per group
#define CHUNK   256                   // candidates per group per smem iteration
#define NITER   (GRANGE / CHUNK)      // 8
#define BUCK_CAP    16                // per-thread staging slots
#define BUCK_FLUSH  8                 // flush when any lane reaches this

// Collapsed weights (device scratch; no allocations allowed)
__device__ float g_W12[LEN_IN * 16];
__device__ float g_Wc [LEN_IN * 6];
__device__ float g_bc [6];

// ---------------------------------------------------------------------------
// Prologue: collapse W1@W2@W3 and the bias chain (tiny, one block).
// The reference MLP has no activation functions, so the whole head is affine:
//   pred = feats @ (W1@W2@W3) + ((b1@W2 + b2)@W3 + b3)
// ---------------------------------------------------------------------------
__global__ void combine_weights_kernel(const float* __restrict__ W1,
                                       const float* __restrict__ b1,
                                       const float* __restrict__ W2,
                                       const float* __restrict__ b2,
                                       const float* __restrict__ W3,
                                       const float* __restrict__ b3)
{
    int t = threadIdx.x;
    // W12 = W1[66,32] @ W2[32,16]
    for (int e = t; e < LEN_IN * 16; e += blockDim.x) {
        int r = e / 16, c = e % 16;
        float s = 0.f;
        for (int k = 0; k < 32; ++k) s += W1[r * 32 + k] * W2[k * 16 + c];
        g_W12[e] = s;
    }
    __syncthreads();
    // Wc = W12[66,16] @ W3[16,6]
    for (int e = t; e < LEN_IN * 6; e += blockDim.x) {
        int r = e / 6, c = e % 6;
        float s = 0.f;
        for (int k = 0; k < 16; ++k) s += g_W12[r * 16 + k] * W3[k * 6 + c];
        g_Wc[e] = s;
    }
    // bc = ((b1@W2)+b2)@W3 + b3
    if (t < 6) {
        float s = b3[t];
        for (int k = 0; k < 16; ++k) {
            float tb = b2[k];
            for (int m = 0; m < 32; ++m) tb += b1[m] * W2[m * 16 + k];
            s += tb * W3[k * 6 + t];
        }
        g_bc[t] = s;
    }
}

// ---------------------------------------------------------------------------
// Main fused kernel: split-K brute-force kNN (top-11 by d2) with staged
// inserts (conflict-free slot-major buckets) + exact merge + gather +
// collapsed linear head.
//   Block = 32 queries x 4 candidate groups (128 threads).
//   Warp w scans candidate range [w*2048, (w+1)*2048) for its 32 queries.
// ---------------------------------------------------------------------------
__global__ void __launch_bounds__(TPB)
knn_mlp_kernel(const float* __restrict__ pos,
               const float* __restrict__ vel,
               const float* __restrict__ initc,
               float* __restrict__ out)
{
    __shared__ float4 s_tile[NGROUP * CHUNK];      // candidate chunks (16KB)
    __shared__ float  s_bdk[BUCK_CAP * TPB];       // staged d2, slot-major (8KB)
    __shared__ int    s_bik[BUCK_CAP * TPB];       // staged idx, slot-major (8KB)
    __shared__ float  s_md[TPB * KNN];             // partial top-11 distances
    __shared__ int    s_mi[TPB * KNN];             // partial top-11 indices
    __shared__ float  s_Wc[LEN_IN * 6];
    __shared__ float  s_bc[6];

    const int tid  = threadIdx.x;
    const int grp  = tid >> 5;                     // 0..3  (== warp id)
    const int qloc = tid & (QPB - 1);              // query within block
    const int q    = blockIdx.x * QPB + qloc;      // global query id
    const int bb   = q >> 13;                      // q / 8192 (batch)
    const int i    = q & (NPTS - 1);

    const float* __restrict__ bpos = pos + (size_t)bb * NPTS * 3;
    const float* __restrict__ bvel = vel + (size_t)bb * NPTS * 3;

    for (int t = tid; t < LEN_IN * 6; t += TPB) s_Wc[t] = g_Wc[t];
    if (tid < 6) s_bc[tid] = g_bc[tid];

    // Query point; sq computed with the SAME op sequence as the tile loader so
    // the self-distance is exactly 0 (round-5 passing recipe, unchanged).
    const float qx = bpos[i * 3 + 0];
    const float qy = bpos[i * 3 + 1];
    const float qz = bpos[i * 3 + 2];
    float qs = qx * qx; qs = fmaf(qy, qy, qs); qs = fmaf(qz, qz, qs);

    // Per-group sorted top-11 (ascending), register-resident.
    float bd[KNN];
    int   bi[KNN];
#pragma unroll
    for (int k = 0; k < KNN; ++k) { bd[k] = CUDART_INF_F; bi[k] = 0; }

    int   cnt = 0;
    float tau = CUDART_INF_F;

    const float4* __restrict__ mytile = s_tile + grp * CHUNK;

    for (int it = 0; it < NITER; ++it) {
        __syncthreads();
        // Cooperative load of all groups' chunks: (x,y,z,sq)
        for (int t = tid; t < NGROUP * CHUNK; t += TPB) {
            const int g  = t >> 8;                        // t / CHUNK
            const int r  = t & (CHUNK - 1);
            const int j  = g * GRANGE + it * CHUNK + r;   // global candidate id
            const float x = bpos[j * 3 + 0];
            const float y = bpos[j * 3 + 1];
            const float z = bpos[j * 3 + 2];
            float s = x * x; s = fmaf(y, y, s); s = fmaf(z, z, s);
            s_tile[t] = make_float4(x, y, z, s);
        }
        __syncthreads();

        const int idxbase = grp * GRANGE + it * CHUNK;
        for (int tb = 0; tb < CHUNK; tb += 8) {
#pragma unroll
            for (int v = 0; v < 8; ++v) {
                const int t = tb + v;
                const float4 p = mytile[t];
                float d = qx * p.x; d = fmaf(qy, p.y, d); d = fmaf(qz, p.z, d);
                const float d2 = fmaf(-2.0f, d, qs + p.w);
                // Cheap staged append; slot-major layout -> bank = tid%32,
                // conflict-free for any mix of per-lane cnt values.
                if (d2 < tau) {
                    s_bdk[cnt * TPB + tid] = d2;
                    s_bik[cnt * TPB + tid] = idxbase + t;
                    ++cnt;
                }
            }
            // Warp-coherent flush when any lane's bucket is half full.
            // (<=8 items can be added between checks; capacity 16 is safe.)
            if (__ballot_sync(0xFFFFFFFFu, cnt >= BUCK_FLUSH)) {
                // Replay staged items in scan order through the EXACT serial
                // strict-'<' chain (round-5/9 passing semantics). Replaying a
                // superset of qualifying candidates is a no-op for the
                // non-qualifying ones, so stale-tau staging is bit-exact.
                for (int u = 0; u < cnt; ++u) {
                    float dv = s_bdk[u * TPB + tid];
                    if (dv < bd[KNN - 1]) {
                        int id = s_bik[u * TPB + tid];
#pragma unroll
                        for (int k = 0; k < KNN; ++k) {
                            if (dv < bd[k]) {
                                float td = bd[k]; bd[k] = dv; dv = td;
                                int   ti = bi[k]; bi[k] = id; id = ti;
                            }
                        }
                    }
                }
                cnt = 0;
                tau = bd[KNN - 1];
            }
        }
    }
    // Flush remaining staged candidates.
    for (int u = 0; u < cnt; ++u) {
        float dv = s_bdk[u * TPB + tid];
        if (dv < bd[KNN - 1]) {
            int id = s_bik[u * TPB + tid];
#pragma unroll
            for (int k = 0; k < KNN; ++k) {
                if (dv < bd[k]) {
                    float td = bd[k]; bd[k] = dv; dv = td;
                    int   ti = bi[k]; bi[k] = id; id = ti;
                }
            }
        }
    }

    // Publish partial lists.
#pragma unroll
    for (int k = 0; k < KNN; ++k) {
        s_md[tid * KNN + k] = bd[k];
        s_mi[tid * KNN + k] = bi[k];
    }
    __syncthreads();

    // Threads 0..31 merge their query's four sorted lists sequentially.
    // On equal d2 the lower group wins (its indices are all lower) —
    // same tie rule as the passing round-9 merge.
    if (tid < QPB) {
        float m1d[KNN]; int m1i[KNN];
        // merge group 0 with group 1
        {
            const int a = (0 * QPB + qloc) * KNN;
            const int b = (1 * QPB + qloc) * KNN;
            int ia = 0, ib = 0;
#pragma unroll
            for (int k = 0; k < KNN; ++k) {
                const float da = s_md[a + ia];
                const float db = s_md[b + ib];
                if (da <= db) { m1d[k] = da; m1i[k] = s_mi[a + ia]; ++ia; }
                else          { m1d[k] = db; m1i[k] = s_mi[b + ib]; ++ib; }
            }
        }
        float m2d[KNN]; int m2i[KNN];
        // merge (0,1) with group 2
        {
            const int b = (2 * QPB + qloc) * KNN;
            int ia = 0, ib = 0;
#pragma unroll
            for (int k = 0; k < KNN; ++k) {
                const float da = m1d[ia];
                const float db = s_md[b + ib];
                if (da <= db) { m2d[k] = da; m2i[k] = m1i[ia]; ++ia; }
                else          { m2d[k] = db; m2i[k] = s_mi[b + ib]; ++ib; }
            }
        }
        int fi[KNN];
        // merge (0,1,2) with group 3
        {
            const int b = (3 * QPB + qloc) * KNN;
            int ia = 0, ib = 0;
#pragma unroll
            for (int k = 0; k < KNN; ++k) {
                const float da = m2d[ia];
                const float db = s_md[b + ib];
                if (da <= db) { fi[k] = m2i[ia]; ++ia; }
                else          { fi[k] = s_mi[b + ib]; ++ib; }
            }
        }

        // ---- gather features and apply collapsed linear head ----
        float acc[6];
#pragma unroll
        for (int c = 0; c < 6; ++c) acc[c] = s_bc[c];

        // rows 0..32: neighbor velocities (incl. self, rank order)
#pragma unroll
        for (int r = 0; r < KNN; ++r) {
            const int j = fi[r];
            const float vx = bvel[j * 3 + 0];
            const float vy = bvel[j * 3 + 1];
            const float vz = bvel[j * 3 + 2];
            const int row = 3 * r;
#pragma unroll
            for (int c = 0; c < 6; ++c) {
                acc[c] = fmaf(vx, s_Wc[(row + 0) * 6 + c], acc[c]);
                acc[c] = fmaf(vy, s_Wc[(row + 1) * 6 + c], acc[c]);
                acc[c] = fmaf(vz, s_Wc[(row + 2) * 6 + c], acc[c]);
            }
        }
        // rows 33..62: neighbor position offsets (excl. self)
#pragma unroll
        for (int r = 1; r < KNN; ++r) {
            const int j = fi[r];
            const float ox = bpos[j * 3 + 0] - qx;
            const float oy = bpos[j * 3 + 1] - qy;
            const float oz = bpos[j * 3 + 2] - qz;
            const int row = 33 + 3 * (r - 1);
#pragma unroll
            for (int c = 0; c < 6; ++c) {
                acc[c] = fmaf(ox, s_Wc[(row + 0) * 6 + c], acc[c]);
                acc[c] = fmaf(oy, s_Wc[(row + 1) * 6 + c], acc[c]);
                acc[c] = fmaf(oz, s_Wc[(row + 2) * 6 + c], acc[c]);
            }
        }
        // rows 63..65: init_config
        {
            const float i0 = initc[bb * 3 + 0];
            const float i1 = initc[bb * 3 + 1];
            const float i2 = initc[bb * 3 + 2];
#pragma unroll
            for (int c = 0; c < 6; ++c) {
                acc[c] = fmaf(i0, s_Wc[63 * 6 + c], acc[c]);
                acc[c] = fmaf(i1, s_Wc[64 * 6 + c], acc[c]);
                acc[c] = fmaf(i2, s_Wc[65 * 6 + c], acc[c]);
            }
        }

        float* o = out + (size_t)q * 6;
        o[0] = acc[0] + qx;
        o[1] = acc[1] + qy;
        o[2] = acc[2] + qz;
        o[3] = acc[3];
        o[4] = acc[4];
        o[5] = acc[5];
    }
}

// ---------------------------------------------------------------------------
extern "C" void kernel_launch(void* const* d_in, const int* in_sizes, int n_in,
                              void* d_out, int out_size)
{
    const float* position = (const float*)d_in[0];
    const float* velocity = (const float*)d_in[1];
    const float* initcfg  = (const float*)d_in[2];
    const float* W1 = (const float*)d_in[3];
    const float* b1 = (const float*)d_in[4];
    const float* W2 = (const float*)d_in[5];
    const float* b2 = (const float*)d_in[6];
    const float* W3 = (const float*)d_in[7];
    const float* b3 = (const float*)d_in[8];
    float* out = (float*)d_out;

    combine_weights_kernel<<<1, 256>>>(W1, b1, W2, b2, W3, b3);

    const int total = BATCH * NPTS;           // 16384 queries
    knn_mlp_kernel<<<total / QPB, TPB>>>(position, velocity, initcfg, out);
}